// round 4
// baseline (speedup 1.0000x reference)
#include <cuda_runtime.h>
#include <cuda_bf16.h>
#include <cstdint>

#define NROWS 8192
#define IN_F  4096
#define OUT_F 4096
#define RANK  1024

#define BM 128
#define BN 128
#define BK 64              // bytes of K per stage (int8)
#define STR 80             // smem row stride in bytes (64 payload + 16 pad)
#define TILE_BYTES (128 * STR)          // 10240
#define BUF_BYTES  (3 * TILE_BYTES)     // A-hi | A-lo | B
#define SMEM_TOTAL (2 * BUF_BYTES)      // 61440, double buffered

// ---------------- scratch (static device globals) ----------------
__device__ signed char g_xh[(size_t)NROWS * IN_F];   // x hi plane (x*4096 = 256*hi+lo)
__device__ signed char g_xl[(size_t)NROWS * IN_F];   // x lo plane
__device__ signed char g_hh[(size_t)NROWS * RANK];   // h hi plane (h*8 = 256*hi+lo)
__device__ signed char g_hl[(size_t)NROWS * RANK];   // h lo plane
__device__ signed char g_vh[(size_t)RANK  * IN_F];   // Vh integer weights (d-128), exact
__device__ signed char g_u [(size_t)OUT_F * RANK];   // U integer weights
__device__ float       g_cs[RANK];                   // Vh_s * S_s * (S_d - S_zp)

// ---------------- prep kernels ----------------
__global__ void k_convert_x(const float* __restrict__ x, int n4) {
    int i = blockIdx.x * blockDim.x + threadIdx.x;
    if (i >= n4) return;
    float4 v = ((const float4*)x)[i];
    float f[4] = {v.x, v.y, v.z, v.w};
    signed char h[4], l[4];
#pragma unroll
    for (int j = 0; j < 4; ++j) {
        float q = fminf(fmaxf(f[j] * 4096.0f, -32512.0f), 32512.0f);
        int s = __float2int_rn(q);
        int lo = (s << 24) >> 24;            // sign-extended low byte
        int hi = (s - lo) >> 8;
        h[j] = (signed char)hi;
        l[j] = (signed char)lo;
    }
    *(char4*)(g_xh + (size_t)i * 4) = make_char4(h[0], h[1], h[2], h[3]);
    *(char4*)(g_xl + (size_t)i * 4) = make_char4(l[0], l[1], l[2], l[3]);
}

template<int W>
__global__ void k_convert_w(const int* __restrict__ src, int n4) {
    int i = blockIdx.x * blockDim.x + threadIdx.x;
    if (i >= n4) return;
    int4 v = ((const int4*)src)[i];
    signed char* dst = (W == 0) ? g_vh : g_u;
    *(char4*)(dst + (size_t)i * 4) =
        make_char4((signed char)(v.x - 128), (signed char)(v.y - 128),
                   (signed char)(v.z - 128), (signed char)(v.w - 128));
}

__global__ void k_colscale(const int* __restrict__ Sd, const float* __restrict__ vhs,
                           const float* __restrict__ ss, const float* __restrict__ szp) {
    int r = blockIdx.x * blockDim.x + threadIdx.x;
    if (r < RANK) g_cs[r] = vhs[0] * ss[0] * ((float)Sd[r] - szp[0]);
}

// ---------------- IMMA helper ----------------
__device__ __forceinline__ void imma(int* d, uint32_t a0, uint32_t a1, uint32_t a2, uint32_t a3,
                                     uint32_t b0, uint32_t b1) {
    asm volatile(
        "mma.sync.aligned.m16n8k32.row.col.s32.s8.s8.s32 "
        "{%0,%1,%2,%3}, {%4,%5,%6,%7}, {%8,%9}, {%0,%1,%2,%3};\n"
        : "+r"(d[0]), "+r"(d[1]), "+r"(d[2]), "+r"(d[3])
        : "r"(a0), "r"(a1), "r"(a2), "r"(a3), "r"(b0), "r"(b1));
}

// ---------------- GEMM (int8 IMMA, interleaved hi/lo sharing B frags) ----------------
// MODE 0: acc = xq @ Vh_int^T (xq = x*4096) ; h*8 quantized -> g_hh/g_hl   (K=4096)
// MODE 1: acc = hq @ U_int^T  (hq = h*8)    ; y = acc*Us/8 + bias -> f32   (K=1024)
template<int MODE>
__global__ void __launch_bounds__(512, 1)
gemm_imma(const float* __restrict__ sc, const float* __restrict__ bias, float* __restrict__ out) {
    constexpr int K = (MODE == 0) ? IN_F : RANK;
    constexpr int T = K / BK;

    extern __shared__ char smem[];

    const int tid  = threadIdx.x;
    const int lane = tid & 31;
    const int wid  = tid >> 5;
    const int wm   = wid & 3;          // 4 warps along M (32 rows each)
    const int wn   = wid >> 2;         // 4 warps along N (32 cols each)
    const int bm   = blockIdx.x * BM;
    const int bn   = blockIdx.y * BN;

    const signed char* Ah = (MODE == 0) ? g_xh : g_hh;
    const signed char* Al = (MODE == 0) ? g_xl : g_hl;
    const signed char* Bw = (MODE == 0) ? g_vh : g_u;

    int accH[2][4][4], accL[2][4][4];
#pragma unroll
    for (int a = 0; a < 2; ++a)
#pragma unroll
        for (int b = 0; b < 4; ++b)
#pragma unroll
            for (int c = 0; c < 4; ++c) { accH[a][b][c] = 0; accL[a][b][c] = 0; }

    // gmem/smem tiling: 512 threads, each moves one 16B vector per region per stage
    const int r   = tid >> 2;          // 0..127 tile row
    const int c16 = (tid & 3) * 16;    // 0/16/32/48 byte offset in row

    uint4 rh, rl, rb;
    {   // prefetch stage 0
        rh = *(const uint4*)(Ah + (size_t)(bm + r) * K + c16);
        rl = *(const uint4*)(Al + (size_t)(bm + r) * K + c16);
        rb = *(const uint4*)(Bw + (size_t)(bn + r) * K + c16);
    }
    *(uint4*)(smem + 0 * TILE_BYTES + r * STR + c16) = rh;
    *(uint4*)(smem + 1 * TILE_BYTES + r * STR + c16) = rl;
    *(uint4*)(smem + 2 * TILE_BYTES + r * STR + c16) = rb;
    __syncthreads();

    for (int t = 0; t < T; ++t) {
        const int cur = t & 1;

        if (t + 1 < T) {               // stage t+1 global loads into regs
            const int k0 = (t + 1) * BK;
            rh = *(const uint4*)(Ah + (size_t)(bm + r) * K + k0 + c16);
            rl = *(const uint4*)(Al + (size_t)(bm + r) * K + k0 + c16);
            rb = *(const uint4*)(Bw + (size_t)(bn + r) * K + k0 + c16);
        }

        const char* base = smem + cur * BUF_BYTES;
        const int fr = lane >> 2;
        const int tg4 = (lane & 3) * 4;
#pragma unroll
        for (int ks = 0; ks < 2; ++ks) {
            const int co = ks * 32 + tg4;
            // B fragments (shared by hi and lo passes)
            uint32_t bf[4][2];
#pragma unroll
            for (int nt = 0; nt < 4; ++nt) {
                const int o = (wn * 32 + nt * 8 + fr) * STR + co;
                bf[nt][0] = *(const uint32_t*)(base + 2 * TILE_BYTES + o);
                bf[nt][1] = *(const uint32_t*)(base + 2 * TILE_BYTES + o + 16);
            }
#pragma unroll
            for (int mt = 0; mt < 2; ++mt) {
                const int o = (wm * 32 + mt * 16 + fr) * STR + co;
                // hi plane
                uint32_t a0 = *(const uint32_t*)(base + o);
                uint32_t a1 = *(const uint32_t*)(base + o + 8 * STR);
                uint32_t a2 = *(const uint32_t*)(base + o + 16);
                uint32_t a3 = *(const uint32_t*)(base + o + 8 * STR + 16);
#pragma unroll
                for (int nt = 0; nt < 4; ++nt)
                    imma(accH[mt][nt], a0, a1, a2, a3, bf[nt][0], bf[nt][1]);
                // lo plane
                a0 = *(const uint32_t*)(base + TILE_BYTES + o);
                a1 = *(const uint32_t*)(base + TILE_BYTES + o + 8 * STR);
                a2 = *(const uint32_t*)(base + TILE_BYTES + o + 16);
                a3 = *(const uint32_t*)(base + TILE_BYTES + o + 8 * STR + 16);
#pragma unroll
                for (int nt = 0; nt < 4; ++nt)
                    imma(accL[mt][nt], a0, a1, a2, a3, bf[nt][0], bf[nt][1]);
            }
        }

        if (t + 1 < T) {
            const char* nb = smem + (1 - cur) * BUF_BYTES;
            *(uint4*)((char*)nb + 0 * TILE_BYTES + r * STR + c16) = rh;
            *(uint4*)((char*)nb + 1 * TILE_BYTES + r * STR + c16) = rl;
            *(uint4*)((char*)nb + 2 * TILE_BYTES + r * STR + c16) = rb;
        }
        __syncthreads();
    }

    // ---------------- epilogue ----------------
    const int fr = lane >> 2;
    const int fc = (lane & 3) * 2;
    const float usc = (MODE == 1) ? (sc[0] * 0.125f) : 0.f;   // 0.02/8 folded

#pragma unroll
    for (int mt = 0; mt < 2; ++mt) {
#pragma unroll
        for (int nt = 0; nt < 4; ++nt) {
            const int row0 = bm + wm * 32 + mt * 16 + fr;
            const int col0 = bn + wn * 32 + nt * 8 + fc;
#pragma unroll
            for (int h = 0; h < 2; ++h) {
                const int row = row0 + h * 8;
                const float f0 = 256.0f * (float)accH[mt][nt][2 * h + 0] + (float)accL[mt][nt][2 * h + 0];
                const float f1 = 256.0f * (float)accH[mt][nt][2 * h + 1] + (float)accL[mt][nt][2 * h + 1];
                if (MODE == 0) {
                    // h_scaled*8 = acc * cs/512 ; quantize to int16 -> hi/lo planes
                    const float q0f = f0 * (g_cs[col0]     * (1.0f / 512.0f));
                    const float q1f = f1 * (g_cs[col0 + 1] * (1.0f / 512.0f));
                    int q0 = __float2int_rn(fminf(fmaxf(q0f, -32500.f), 32500.f));
                    int q1 = __float2int_rn(fminf(fmaxf(q1f, -32500.f), 32500.f));
                    int lo0 = (q0 << 24) >> 24, hi0 = (q0 - lo0) >> 8;
                    int lo1 = (q1 << 24) >> 24, hi1 = (q1 - lo1) >> 8;
                    *(char2*)(g_hh + (size_t)row * RANK + col0) =
                        make_char2((signed char)hi0, (signed char)hi1);
                    *(char2*)(g_hl + (size_t)row * RANK + col0) =
                        make_char2((signed char)lo0, (signed char)lo1);
                } else {
                    float2 y;
                    y.x = f0 * usc + bias[col0];
                    y.y = f1 * usc + bias[col0 + 1];
                    *(float2*)(out + (size_t)row * OUT_F + col0) = y;
                }
            }
        }
    }
}

// ---------------- launch ----------------
extern "C" void kernel_launch(void* const* d_in, const int* in_sizes, int n_in,
                              void* d_out, int out_size) {
    const float* x    = (const float*)d_in[0];
    const int*   Ud   = (const int*)  d_in[1];
    const float* Us   = (const float*)d_in[2];
    const int*   Sd   = (const int*)  d_in[4];
    const float* Ss   = (const float*)d_in[5];
    const float* Szp  = (const float*)d_in[6];
    const int*   Vhd  = (const int*)  d_in[7];
    const float* Vhs  = (const float*)d_in[8];
    const float* bias = (const float*)d_in[10];
    float* out = (float*)d_out;
    (void)in_sizes; (void)n_in; (void)out_size;

    static bool attr_set = false;
    if (!attr_set) {
        cudaFuncSetAttribute(gemm_imma<0>, cudaFuncAttributeMaxDynamicSharedMemorySize, SMEM_TOTAL);
        cudaFuncSetAttribute(gemm_imma<1>, cudaFuncAttributeMaxDynamicSharedMemorySize, SMEM_TOTAL);
        attr_set = true;
    }

    const int nx4 = NROWS * IN_F / 4;
    k_convert_x<<<(nx4 + 255) / 256, 256>>>(x, nx4);
    k_convert_w<0><<<(RANK * IN_F / 4 + 255) / 256, 256>>>(Vhd, RANK * IN_F / 4);
    k_convert_w<1><<<(OUT_F * RANK / 4 + 255) / 256, 256>>>(Ud, OUT_F * RANK / 4);
    k_colscale<<<(RANK + 255) / 256, 256>>>(Sd, Vhs, Ss, Szp);

    gemm_imma<0><<<dim3(NROWS / BM, RANK  / BN), 512, SMEM_TOTAL>>>(nullptr, nullptr, nullptr);
    gemm_imma<1><<<dim3(NROWS / BM, OUT_F / BN), 512, SMEM_TOTAL>>>(Us, bias, out);
}

// round 5
// speedup vs baseline: 2.7168x; 2.7168x over previous
#include <cuda_runtime.h>
#include <cuda_fp16.h>
#include <cstdint>

#define NROWS 8192
#define IN_F  4096
#define OUT_F 4096
#define RANK  1024

#define BM 128
#define BN 256
#define BK 32                 // fp16 elems of K per stage
#define STRB 80               // smem row stride bytes (64 payload + 16 pad)
#define A_TILE (128 * STRB)   // 10240 B per A plane
#define B_TILE (256 * STRB)   // 20480 B
#define STAGES 3

// ---------------- scratch ----------------
__device__ __half g_xh[(size_t)NROWS * IN_F];   // x hi plane (fp16)
__device__ __half g_xl[(size_t)NROWS * IN_F];   // x lo plane (fp16 residual)
__device__ __half g_h [(size_t)NROWS * RANK];   // h*cs, single fp16 plane
__device__ __half g_vh[(size_t)RANK  * IN_F];   // Vh integer weights (exact fp16)
__device__ __half g_u [(size_t)OUT_F * RANK];   // U integer weights
__device__ float  g_cs[RANK];                   // Vh_s * S_s * (S_d - S_zp)

// ---------------- prep ----------------
__global__ void k_convert_x(const float* __restrict__ x, int n4) {
    int i = blockIdx.x * blockDim.x + threadIdx.x;
    if (i >= n4) return;
    float4 v = ((const float4*)x)[i];
    float f[4] = {v.x, v.y, v.z, v.w};
    __half h[4], l[4];
#pragma unroll
    for (int j = 0; j < 4; ++j) {
        h[j] = __float2half_rn(f[j]);
        l[j] = __float2half_rn(f[j] - __half2float(h[j]));
    }
    *(__half2*)(g_xh + (size_t)i * 4)     = __halves2half2(h[0], h[1]);
    *(__half2*)(g_xh + (size_t)i * 4 + 2) = __halves2half2(h[2], h[3]);
    *(__half2*)(g_xl + (size_t)i * 4)     = __halves2half2(l[0], l[1]);
    *(__half2*)(g_xl + (size_t)i * 4 + 2) = __halves2half2(l[2], l[3]);
}
template<int W>
__global__ void k_convert_w(const int* __restrict__ src, int n4) {
    int i = blockIdx.x * blockDim.x + threadIdx.x;
    if (i >= n4) return;
    int4 v = ((const int4*)src)[i];
    __half* dst = (W == 0) ? g_vh : g_u;
    *(__half2*)(dst + (size_t)i * 4)     = __halves2half2(__int2half_rn(v.x - 128), __int2half_rn(v.y - 128));
    *(__half2*)(dst + (size_t)i * 4 + 2) = __halves2half2(__int2half_rn(v.z - 128), __int2half_rn(v.w - 128));
}
__global__ void k_colscale(const int* __restrict__ Sd, const float* __restrict__ vhs,
                           const float* __restrict__ ss, const float* __restrict__ szp) {
    int r = blockIdx.x * blockDim.x + threadIdx.x;
    if (r < RANK) g_cs[r] = vhs[0] * ss[0] * ((float)Sd[r] - szp[0]);
}

// ---------------- PTX helpers ----------------
__device__ __forceinline__ void cp16(uint32_t dst, const void* src) {
    asm volatile("cp.async.cg.shared.global [%0], [%1], 16;" :: "r"(dst), "l"(src) : "memory");
}
#define CP_COMMIT() asm volatile("cp.async.commit_group;" ::: "memory")
#define CP_WAIT1()  asm volatile("cp.async.wait_group 1;" ::: "memory")
__device__ __forceinline__ uint32_t smem_u32(const void* p) {
    uint32_t a;
    asm("{ .reg .u64 t; cvta.to.shared.u64 t, %1; cvt.u32.u64 %0, t; }" : "=r"(a) : "l"(p));
    return a;
}
__device__ __forceinline__ void hmma(float* d, uint32_t a0, uint32_t a1, uint32_t a2, uint32_t a3,
                                     uint32_t b0, uint32_t b1) {
    asm volatile(
        "mma.sync.aligned.m16n8k16.row.col.f32.f16.f16.f32 "
        "{%0,%1,%2,%3}, {%4,%5,%6,%7}, {%8,%9}, {%0,%1,%2,%3};\n"
        : "+f"(d[0]), "+f"(d[1]), "+f"(d[2]), "+f"(d[3])
        : "r"(a0), "r"(a1), "r"(a2), "r"(a3), "r"(b0), "r"(b1));
}
__device__ __forceinline__ uint32_t lds32(uint32_t addr) {
    uint32_t v;
    asm volatile("ld.shared.b32 %0, [%1];" : "=r"(v) : "r"(addr));
    return v;
}

// ---------------- GEMM ----------------
// MODE 0: acc = (xh+xl) @ Vh^T ; h = acc*cs -> g_h (fp16)        (K=4096, 2 planes)
// MODE 1: acc = h @ U^T ; y = acc*Us + bias -> f32 out           (K=1024, 1 plane)
template<int MODE>
__global__ void __launch_bounds__(256, 1)
gemm_hmma(const float* __restrict__ sc, const float* __restrict__ bias, float* __restrict__ out) {
    constexpr int K        = (MODE == 0) ? IN_F : RANK;
    constexpr int T        = K / BK;
    constexpr int NPLANES  = (MODE == 0) ? 2 : 1;
    constexpr int B_OFF    = NPLANES * A_TILE;
    constexpr int STG_B    = B_OFF + B_TILE;

    extern __shared__ char smem[];
    const uint32_t sb = smem_u32(smem);

    const int tid  = threadIdx.x;
    const int lane = tid & 31;
    const int wid  = tid >> 5;
    const int wm   = wid & 1;           // 2 warp-rows (64 M each)
    const int wn   = wid >> 1;          // 4 warp-cols (64 N each)
    const int bm   = blockIdx.x * BM;
    const int bn   = blockIdx.y * BN;

    const __half* Ah = (MODE == 0) ? g_xh : g_h;
    const __half* Al = g_xl;            // unused in MODE 1
    const __half* Bw = (MODE == 0) ? g_vh : g_u;

    float acc[4][8][4];
#pragma unroll
    for (int a = 0; a < 4; ++a)
#pragma unroll
        for (int b = 0; b < 8; ++b)
#pragma unroll
            for (int c = 0; c < 4; ++c) acc[a][b][c] = 0.f;

    // per-thread load slots: r0 = tid>>2 (0..63), c0 = tid&3 (16B chunk in row)
    const int r0 = tid >> 2;
    const int c0 = tid & 3;

    auto issue_stage = [&](int t) {
        const int s = t % STAGES;
        const uint32_t stg = sb + s * STG_B;
        const int k0 = t * BK;
        const size_t ao = (size_t)(bm + r0) * K + k0 + c0 * 8;
        const size_t ao2 = ao + (size_t)64 * K;
        const uint32_t da = stg + r0 * STRB + c0 * 16;
        cp16(da,                    Ah + ao);
        cp16(da + 64 * STRB,        Ah + ao2);
        if (MODE == 0) {
            cp16(da + A_TILE,            Al + ao);
            cp16(da + A_TILE + 64 * STRB, Al + ao2);
        }
        const size_t bo = (size_t)(bn + r0) * K + k0 + c0 * 8;
        const uint32_t db = stg + B_OFF + r0 * STRB + c0 * 16;
#pragma unroll
        for (int q = 0; q < 4; ++q)
            cp16(db + q * 64 * STRB, Bw + bo + (size_t)q * 64 * K);
    };

    issue_stage(0); CP_COMMIT();
    issue_stage(1); CP_COMMIT();

    const int fr = lane >> 2;
    const int fq = (lane & 3) * 2;

    for (int t = 0; t < T; ++t) {
        CP_WAIT1();
        __syncthreads();
        if (t + 2 < T) issue_stage(t + 2);
        CP_COMMIT();

        const uint32_t stg = sb + (t % STAGES) * STG_B;
#pragma unroll
        for (int ks = 0; ks < 2; ++ks) {
            const int co = (ks * 16 + fq) * 2;      // byte offset of k-col
            // B frags: 64 cols (8 n-tiles), shared by both planes
            uint32_t bf[8][2];
#pragma unroll
            for (int nt = 0; nt < 8; ++nt) {
                const uint32_t o = stg + B_OFF + (wn * 64 + nt * 8 + fr) * STRB + co;
                bf[nt][0] = lds32(o);
                bf[nt][1] = lds32(o + 16);
            }
#pragma unroll
            for (int p = 0; p < NPLANES; ++p) {
                const uint32_t ab = stg + p * A_TILE;
#pragma unroll
                for (int mt = 0; mt < 4; ++mt) {
                    const uint32_t o = ab + (wm * 64 + mt * 16 + fr) * STRB + co;
                    const uint32_t a0 = lds32(o);
                    const uint32_t a1 = lds32(o + 8 * STRB);
                    const uint32_t a2 = lds32(o + 16);
                    const uint32_t a3 = lds32(o + 8 * STRB + 16);
#pragma unroll
                    for (int nt = 0; nt < 8; ++nt)
                        hmma(acc[mt][nt], a0, a1, a2, a3, bf[nt][0], bf[nt][1]);
                }
            }
        }
        __syncthreads();
    }

    // ---------------- epilogue ----------------
    const float us = (MODE == 1) ? sc[0] : 0.f;
#pragma unroll
    for (int mt = 0; mt < 4; ++mt) {
#pragma unroll
        for (int nt = 0; nt < 8; ++nt) {
            const int row0 = bm + wm * 64 + mt * 16 + fr;
            const int col0 = bn + wn * 64 + nt * 8 + fq;
#pragma unroll
            for (int h = 0; h < 2; ++h) {
                const int row = row0 + h * 8;
                const float v0 = acc[mt][nt][2 * h + 0];
                const float v1 = acc[mt][nt][2 * h + 1];
                if (MODE == 0) {
                    const float s0 = g_cs[col0], s1 = g_cs[col0 + 1];
                    *(__half2*)(g_h + (size_t)row * RANK + col0) =
                        __halves2half2(__float2half_rn(v0 * s0), __float2half_rn(v1 * s1));
                } else {
                    float2 y;
                    y.x = v0 * us + bias[col0];
                    y.y = v1 * us + bias[col0 + 1];
                    *(float2*)(out + (size_t)row * OUT_F + col0) = y;
                }
            }
        }
    }
}

// ---------------- launch ----------------
extern "C" void kernel_launch(void* const* d_in, const int* in_sizes, int n_in,
                              void* d_out, int out_size) {
    const float* x    = (const float*)d_in[0];
    const int*   Ud   = (const int*)  d_in[1];
    const float* Us   = (const float*)d_in[2];
    const int*   Sd   = (const int*)  d_in[4];
    const float* Ss   = (const float*)d_in[5];
    const float* Szp  = (const float*)d_in[6];
    const int*   Vhd  = (const int*)  d_in[7];
    const float* Vhs  = (const float*)d_in[8];
    const float* bias = (const float*)d_in[10];
    float* out = (float*)d_out;
    (void)in_sizes; (void)n_in; (void)out_size;

    const int smem0 = STAGES * (2 * A_TILE + B_TILE);   // 122880
    const int smem1 = STAGES * (1 * A_TILE + B_TILE);   // 92160
    cudaFuncSetAttribute(gemm_hmma<0>, cudaFuncAttributeMaxDynamicSharedMemorySize, smem0);
    cudaFuncSetAttribute(gemm_hmma<1>, cudaFuncAttributeMaxDynamicSharedMemorySize, smem1);

    const int nx4 = NROWS * IN_F / 4;
    k_convert_x<<<(nx4 + 255) / 256, 256>>>(x, nx4);
    k_convert_w<0><<<(RANK * IN_F / 4 + 255) / 256, 256>>>(Vhd, RANK * IN_F / 4);
    k_convert_w<1><<<(OUT_F * RANK / 4 + 255) / 256, 256>>>(Ud, OUT_F * RANK / 4);
    k_colscale<<<(RANK + 255) / 256, 256>>>(Sd, Vhs, Ss, Szp);

    gemm_hmma<0><<<dim3(NROWS / BM, RANK  / BN), 256, smem0>>>(nullptr, nullptr, nullptr);
    gemm_hmma<1><<<dim3(NROWS / BM, OUT_F / BN), 256, smem1>>>(Us, bias, out);
}

// round 6
// speedup vs baseline: 3.6584x; 1.3465x over previous
#include <cuda_runtime.h>
#include <cuda_fp16.h>
#include <cstdint>

#define NROWS 8192
#define IN_F  4096
#define OUT_F 4096
#define RANK  1024

#define BM 128
#define BN 256
#define BK 32                 // fp16 elems of K per stage
#define STRB 80               // smem row stride bytes (64 payload + 16 pad)
#define A_TILE (128 * STRB)   // 10240 B
#define B_TILE (256 * STRB)   // 20480 B
#define STG_B  (A_TILE + B_TILE)
#define STAGES 3
#define SMEM_TOTAL (STAGES * STG_B)   // 92160

// ---------------- scratch ----------------
__device__ __half g_x [(size_t)NROWS * IN_F];   // x (fp16, single plane)
__device__ __half g_h [(size_t)NROWS * RANK];   // h*cs (fp16)
__device__ __half g_vh[(size_t)RANK  * IN_F];   // Vh integer weights (exact fp16)
__device__ __half g_u [(size_t)OUT_F * RANK];   // U integer weights
__device__ float  g_cs[RANK];                   // Vh_s * S_s * (S_d - S_zp)

// ---------------- prep ----------------
__global__ void k_convert_x(const float* __restrict__ x, int n4) {
    int i = blockIdx.x * blockDim.x + threadIdx.x;
    if (i >= n4) return;
    float4 v = ((const float4*)x)[i];
    *(__half2*)(g_x + (size_t)i * 4)     = __halves2half2(__float2half_rn(v.x), __float2half_rn(v.y));
    *(__half2*)(g_x + (size_t)i * 4 + 2) = __halves2half2(__float2half_rn(v.z), __float2half_rn(v.w));
}
template<int W>
__global__ void k_convert_w(const int* __restrict__ src, int n4) {
    int i = blockIdx.x * blockDim.x + threadIdx.x;
    if (i >= n4) return;
    int4 v = ((const int4*)src)[i];
    __half* dst = (W == 0) ? g_vh : g_u;
    *(__half2*)(dst + (size_t)i * 4)     = __halves2half2(__int2half_rn(v.x - 128), __int2half_rn(v.y - 128));
    *(__half2*)(dst + (size_t)i * 4 + 2) = __halves2half2(__int2half_rn(v.z - 128), __int2half_rn(v.w - 128));
}
__global__ void k_colscale(const int* __restrict__ Sd, const float* __restrict__ vhs,
                           const float* __restrict__ ss, const float* __restrict__ szp) {
    int r = blockIdx.x * blockDim.x + threadIdx.x;
    if (r < RANK) g_cs[r] = vhs[0] * ss[0] * ((float)Sd[r] - szp[0]);
}

// ---------------- PTX helpers ----------------
__device__ __forceinline__ void cp16(uint32_t dst, const void* src) {
    asm volatile("cp.async.cg.shared.global [%0], [%1], 16;" :: "r"(dst), "l"(src) : "memory");
}
#define CP_COMMIT() asm volatile("cp.async.commit_group;" ::: "memory")
#define CP_WAIT1()  asm volatile("cp.async.wait_group 1;" ::: "memory")
__device__ __forceinline__ uint32_t smem_u32(const void* p) {
    uint32_t a;
    asm("{ .reg .u64 t; cvta.to.shared.u64 t, %1; cvt.u32.u64 %0, t; }" : "=r"(a) : "l"(p));
    return a;
}
__device__ __forceinline__ void hmma(float* d, uint32_t a0, uint32_t a1, uint32_t a2, uint32_t a3,
                                     uint32_t b0, uint32_t b1) {
    asm volatile(
        "mma.sync.aligned.m16n8k16.row.col.f32.f16.f16.f32 "
        "{%0,%1,%2,%3}, {%4,%5,%6,%7}, {%8,%9}, {%0,%1,%2,%3};\n"
        : "+f"(d[0]), "+f"(d[1]), "+f"(d[2]), "+f"(d[3])
        : "r"(a0), "r"(a1), "r"(a2), "r"(a3), "r"(b0), "r"(b1));
}
__device__ __forceinline__ void ldsm4(uint32_t& r0, uint32_t& r1, uint32_t& r2, uint32_t& r3,
                                      uint32_t addr) {
    asm volatile("ldmatrix.sync.aligned.m8n8.x4.shared.b16 {%0,%1,%2,%3}, [%4];"
                 : "=r"(r0), "=r"(r1), "=r"(r2), "=r"(r3) : "r"(addr));
}

// ---------------- GEMM ----------------
// MODE 0: h = (x @ Vh^T) * cs -> g_h (fp16)          K=4096
// MODE 1: y = (h @ U^T) * Us + bias -> f32 out       K=1024
template<int MODE>
__global__ void __launch_bounds__(256, 1)
gemm_hmma(const float* __restrict__ sc, const float* __restrict__ bias, float* __restrict__ out) {
    constexpr int K = (MODE == 0) ? IN_F : RANK;
    constexpr int T = K / BK;

    extern __shared__ char smem[];
    const uint32_t sb = smem_u32(smem);

    const int tid  = threadIdx.x;
    const int lane = tid & 31;
    const int wid  = tid >> 5;
    const int wm   = wid & 1;           // 2 warp-rows (64 M each)
    const int wn   = wid >> 1;          // 4 warp-cols (64 N each)
    const int bm   = blockIdx.x * BM;
    const int bn   = blockIdx.y * BN;

    const __half* Ap = (MODE == 0) ? g_x  : g_h;
    const __half* Bw = (MODE == 0) ? g_vh : g_u;

    float acc[4][8][4];
#pragma unroll
    for (int a = 0; a < 4; ++a)
#pragma unroll
        for (int b = 0; b < 8; ++b)
#pragma unroll
            for (int c = 0; c < 4; ++c) acc[a][b][c] = 0.f;

    // ---- producer mapping: 256 threads, 16B chunks ----
    const int r0 = tid >> 2;            // 0..63
    const int c0 = tid & 3;             // 16B chunk in 64B row

    auto issue_stage = [&](int t) {
        const uint32_t stg = sb + (t % STAGES) * STG_B;
        const int k0 = t * BK;
        const size_t ao = (size_t)(bm + r0) * K + k0 + c0 * 8;
        const uint32_t da = stg + r0 * STRB + c0 * 16;
        cp16(da,             Ap + ao);
        cp16(da + 64 * STRB, Ap + ao + (size_t)64 * K);
        const size_t bo = (size_t)(bn + r0) * K + k0 + c0 * 8;
        const uint32_t db = stg + A_TILE + r0 * STRB + c0 * 16;
#pragma unroll
        for (int q = 0; q < 4; ++q)
            cp16(db + q * 64 * STRB, Bw + bo + (size_t)q * 64 * K);
    };

    issue_stage(0); CP_COMMIT();
    issue_stage(1); CP_COMMIT();

    // ---- ldmatrix per-lane base offsets ----
    const int grp = lane >> 3, win = lane & 7;
    // A x4: regs = tiles (0,0),(8,0),(0,8),(8,8): lanes g0:r+0 k+0 | g1:r+8 k+0 | g2:r+0 k+16 | g3:r+8 k+16
    const uint32_t aoff = (wm * 64 + ((grp & 1) << 3) + win) * STRB + ((grp >> 1) << 4);
    // B x4: regs = nt0 k0 | nt0 k16 | nt1 k0 | nt1 k16: lanes g0:n+0 k+0 | g1:n+0 k+16 | g2:n+8 k+0 | g3:n+8 k+16
    const uint32_t boff = A_TILE + (wn * 64 + ((grp >> 1) << 3) + win) * STRB + ((grp & 1) << 4);

    for (int t = 0; t < T; ++t) {
        CP_WAIT1();
        __syncthreads();
        if (t + 2 < T) issue_stage(t + 2);
        CP_COMMIT();

        const uint32_t stg = sb + (t % STAGES) * STG_B;
#pragma unroll
        for (int ks = 0; ks < 2; ++ks) {
            const uint32_t co = ks * 32;
            uint32_t bf[8][2];
#pragma unroll
            for (int ntp = 0; ntp < 4; ++ntp)
                ldsm4(bf[2*ntp][0], bf[2*ntp][1], bf[2*ntp+1][0], bf[2*ntp+1][1],
                      stg + boff + ntp * 16 * STRB + co);
#pragma unroll
            for (int mt = 0; mt < 4; ++mt) {
                uint32_t a0, a1, a2, a3;
                ldsm4(a0, a1, a2, a3, stg + aoff + mt * 16 * STRB + co);
#pragma unroll
                for (int nt = 0; nt < 8; ++nt)
                    hmma(acc[mt][nt], a0, a1, a2, a3, bf[nt][0], bf[nt][1]);
            }
        }
    }

    // ---------------- epilogue ----------------
    const int fr = lane >> 2;
    const int fq = (lane & 3) * 2;
    const float us = (MODE == 1) ? sc[0] : 0.f;
#pragma unroll
    for (int mt = 0; mt < 4; ++mt) {
#pragma unroll
        for (int nt = 0; nt < 8; ++nt) {
            const int row0 = bm + wm * 64 + mt * 16 + fr;
            const int col0 = bn + wn * 64 + nt * 8 + fq;
#pragma unroll
            for (int h = 0; h < 2; ++h) {
                const int row = row0 + h * 8;
                const float v0 = acc[mt][nt][2 * h + 0];
                const float v1 = acc[mt][nt][2 * h + 1];
                if (MODE == 0) {
                    *(__half2*)(g_h + (size_t)row * RANK + col0) =
                        __halves2half2(__float2half_rn(v0 * g_cs[col0]),
                                       __float2half_rn(v1 * g_cs[col0 + 1]));
                } else {
                    float2 y;
                    y.x = v0 * us + bias[col0];
                    y.y = v1 * us + bias[col0 + 1];
                    *(float2*)(out + (size_t)row * OUT_F + col0) = y;
                }
            }
        }
    }
}

// ---------------- launch ----------------
extern "C" void kernel_launch(void* const* d_in, const int* in_sizes, int n_in,
                              void* d_out, int out_size) {
    const float* x    = (const float*)d_in[0];
    const int*   Ud   = (const int*)  d_in[1];
    const float* Us   = (const float*)d_in[2];
    const int*   Sd   = (const int*)  d_in[4];
    const float* Ss   = (const float*)d_in[5];
    const float* Szp  = (const float*)d_in[6];
    const int*   Vhd  = (const int*)  d_in[7];
    const float* Vhs  = (const float*)d_in[8];
    const float* bias = (const float*)d_in[10];
    float* out = (float*)d_out;
    (void)in_sizes; (void)n_in; (void)out_size;

    cudaFuncSetAttribute(gemm_hmma<0>, cudaFuncAttributeMaxDynamicSharedMemorySize, SMEM_TOTAL);
    cudaFuncSetAttribute(gemm_hmma<1>, cudaFuncAttributeMaxDynamicSharedMemorySize, SMEM_TOTAL);

    const int nx4 = NROWS * IN_F / 4;
    k_convert_x<<<(nx4 + 255) / 256, 256>>>(x, nx4);
    k_convert_w<0><<<(RANK * IN_F / 4 + 255) / 256, 256>>>(Vhd, RANK * IN_F / 4);
    k_convert_w<1><<<(OUT_F * RANK / 4 + 255) / 256, 256>>>(Ud, OUT_F * RANK / 4);
    k_colscale<<<(RANK + 255) / 256, 256>>>(Sd, Vhs, Ss, Szp);

    gemm_hmma<0><<<dim3(NROWS / BM, RANK  / BN), 256, SMEM_TOTAL>>>(nullptr, nullptr, nullptr);
    gemm_hmma<1><<<dim3(NROWS / BM, OUT_F / BN), 256, SMEM_TOTAL>>>(Us, bias, out);
}

// round 7
// speedup vs baseline: 3.8716x; 1.0583x over previous
#include <cuda_runtime.h>
#include <cuda_fp16.h>
#include <cstdint>

#define NROWS 8192
#define IN_F  4096
#define OUT_F 4096
#define RANK  1024

#define BM 128
#define BN 256
#define BK 32
#define STRB 80
#define A_TILE (128 * STRB)
#define B_TILE (256 * STRB)
#define STG_B  (A_TILE + B_TILE)
#define STAGES 3
#define SMEM_TOTAL (STAGES * STG_B)   // 92160

#define G1_TASKS 256                  // 64 m x 4 n
#define G2_TASKS 1024                 // 64 m x 16 n
#define NTASKS   (G1_TASKS + G2_TASKS)
#define PERSIST  152

// ---------------- scratch ----------------
__device__ __half g_x [(size_t)NROWS * IN_F];
__device__ __half g_h [(size_t)NROWS * RANK];
__device__ __half g_vh[(size_t)RANK  * IN_F];
__device__ __half g_u [(size_t)OUT_F * RANK];
__device__ float  g_cs[RANK];
__device__ unsigned g_ticket;
__device__ unsigned g_flag[64];       // per m-block: # of finished G1 tiles (target 4)

// ---------------- prep ----------------
__global__ void k_init() {
    if (threadIdx.x == 0) g_ticket = 0;
    if (threadIdx.x < 64) g_flag[threadIdx.x] = 0;
}
__global__ void k_convert_x(const float* __restrict__ x, int n4) {
    int i = blockIdx.x * blockDim.x + threadIdx.x;
    if (i >= n4) return;
    float4 v = ((const float4*)x)[i];
    *(__half2*)(g_x + (size_t)i * 4)     = __halves2half2(__float2half_rn(v.x), __float2half_rn(v.y));
    *(__half2*)(g_x + (size_t)i * 4 + 2) = __halves2half2(__float2half_rn(v.z), __float2half_rn(v.w));
}
__global__ void k_convert_w2(const int* __restrict__ Vhd, const int* __restrict__ Ud) {
    const int nv = RANK * IN_F / 4;
    const int nu = OUT_F * RANK / 4;
    int i = blockIdx.x * blockDim.x + threadIdx.x;
    const int* src; __half* dst; int j;
    if (i < nv)           { src = Vhd; dst = g_vh; j = i; }
    else if (i < nv + nu) { src = Ud;  dst = g_u;  j = i - nv; }
    else return;
    int4 v = ((const int4*)src)[j];
    *(__half2*)(dst + (size_t)j * 4)     = __halves2half2(__int2half_rn(v.x - 128), __int2half_rn(v.y - 128));
    *(__half2*)(dst + (size_t)j * 4 + 2) = __halves2half2(__int2half_rn(v.z - 128), __int2half_rn(v.w - 128));
}
__global__ void k_colscale(const int* __restrict__ Sd, const float* __restrict__ vhs,
                           const float* __restrict__ ss, const float* __restrict__ szp) {
    int r = blockIdx.x * blockDim.x + threadIdx.x;
    if (r < RANK) g_cs[r] = vhs[0] * ss[0] * ((float)Sd[r] - szp[0]);
}

// ---------------- PTX helpers ----------------
__device__ __forceinline__ void cp16(uint32_t dst, const void* src) {
    asm volatile("cp.async.cg.shared.global [%0], [%1], 16;" :: "r"(dst), "l"(src) : "memory");
}
#define CP_COMMIT() asm volatile("cp.async.commit_group;" ::: "memory")
#define CP_WAIT1()  asm volatile("cp.async.wait_group 1;" ::: "memory")
#define CP_WAIT0()  asm volatile("cp.async.wait_group 0;" ::: "memory")
__device__ __forceinline__ uint32_t smem_u32(const void* p) {
    uint32_t a;
    asm("{ .reg .u64 t; cvta.to.shared.u64 t, %1; cvt.u32.u64 %0, t; }" : "=r"(a) : "l"(p));
    return a;
}
__device__ __forceinline__ void hmma(float* d, uint32_t a0, uint32_t a1, uint32_t a2, uint32_t a3,
                                     uint32_t b0, uint32_t b1) {
    asm volatile(
        "mma.sync.aligned.m16n8k16.row.col.f32.f16.f16.f32 "
        "{%0,%1,%2,%3}, {%4,%5,%6,%7}, {%8,%9}, {%0,%1,%2,%3};\n"
        : "+f"(d[0]), "+f"(d[1]), "+f"(d[2]), "+f"(d[3])
        : "r"(a0), "r"(a1), "r"(a2), "r"(a3), "r"(b0), "r"(b1));
}
__device__ __forceinline__ void ldsm4(uint32_t& r0, uint32_t& r1, uint32_t& r2, uint32_t& r3,
                                      uint32_t addr) {
    asm volatile("ldmatrix.sync.aligned.m8n8.x4.shared.b16 {%0,%1,%2,%3}, [%4];"
                 : "=r"(r0), "=r"(r1), "=r"(r2), "=r"(r3) : "r"(addr));
}

// ---------------- one GEMM tile task (r6 inner loop, unchanged) ----------------
// MODE 0: h = (x @ Vh^T) * cs -> g_h (fp16)      K=4096
// MODE 1: y = (h @ U^T) * Us + bias -> out f32   K=1024
template<int MODE>
__device__ __forceinline__ void run_tile(uint32_t sb, int bm, int bn,
                                         float us, const float* __restrict__ bias,
                                         float* __restrict__ out) {
    constexpr int K = (MODE == 0) ? IN_F : RANK;
    constexpr int T = K / BK;

    const int tid  = threadIdx.x;
    const int lane = tid & 31;
    const int wid  = tid >> 5;
    const int wm   = wid & 1;
    const int wn   = wid >> 1;

    const __half* Ap = (MODE == 0) ? g_x  : g_h;
    const __half* Bw = (MODE == 0) ? g_vh : g_u;

    float acc[4][8][4];
#pragma unroll
    for (int a = 0; a < 4; ++a)
#pragma unroll
        for (int b = 0; b < 8; ++b)
#pragma unroll
            for (int c = 0; c < 4; ++c) acc[a][b][c] = 0.f;

    const int r0 = tid >> 2;
    const int c0 = tid & 3;

    auto issue_stage = [&](int t) {
        const uint32_t stg = sb + (t % STAGES) * STG_B;
        const int k0 = t * BK;
        const size_t ao = (size_t)(bm + r0) * K + k0 + c0 * 8;
        const uint32_t da = stg + r0 * STRB + c0 * 16;
        cp16(da,             Ap + ao);
        cp16(da + 64 * STRB, Ap + ao + (size_t)64 * K);
        const size_t bo = (size_t)(bn + r0) * K + k0 + c0 * 8;
        const uint32_t db = stg + A_TILE + r0 * STRB + c0 * 16;
#pragma unroll
        for (int q = 0; q < 4; ++q)
            cp16(db + q * 64 * STRB, Bw + bo + (size_t)q * 64 * K);
    };

    issue_stage(0); CP_COMMIT();
    issue_stage(1); CP_COMMIT();

    const int grp = lane >> 3, win = lane & 7;
    const uint32_t aoff = (wm * 64 + ((grp & 1) << 3) + win) * STRB + ((grp >> 1) << 4);
    const uint32_t boff = A_TILE + (wn * 64 + ((grp >> 1) << 3) + win) * STRB + ((grp & 1) << 4);

    for (int t = 0; t < T; ++t) {
        CP_WAIT1();
        __syncthreads();
        if (t + 2 < T) issue_stage(t + 2);
        CP_COMMIT();

        const uint32_t stg = sb + (t % STAGES) * STG_B;
#pragma unroll
        for (int ks = 0; ks < 2; ++ks) {
            const uint32_t co = ks * 32;
            uint32_t bf[8][2];
#pragma unroll
            for (int ntp = 0; ntp < 4; ++ntp)
                ldsm4(bf[2*ntp][0], bf[2*ntp][1], bf[2*ntp+1][0], bf[2*ntp+1][1],
                      stg + boff + ntp * 16 * STRB + co);
#pragma unroll
            for (int mt = 0; mt < 4; ++mt) {
                uint32_t a0, a1, a2, a3;
                ldsm4(a0, a1, a2, a3, stg + aoff + mt * 16 * STRB + co);
#pragma unroll
                for (int nt = 0; nt < 8; ++nt)
                    hmma(acc[mt][nt], a0, a1, a2, a3, bf[nt][0], bf[nt][1]);
            }
        }
    }
    CP_WAIT0();   // drain outstanding prefetches before smem is reused by next task

    const int fr = lane >> 2;
    const int fq = (lane & 3) * 2;
#pragma unroll
    for (int mt = 0; mt < 4; ++mt) {
#pragma unroll
        for (int nt = 0; nt < 8; ++nt) {
            const int row0 = bm + wm * 64 + mt * 16 + fr;
            const int col0 = bn + wn * 64 + nt * 8 + fq;
#pragma unroll
            for (int h = 0; h < 2; ++h) {
                const int row = row0 + h * 8;
                const float v0 = acc[mt][nt][2 * h + 0];
                const float v1 = acc[mt][nt][2 * h + 1];
                if (MODE == 0) {
                    *(__half2*)(g_h + (size_t)row * RANK + col0) =
                        __halves2half2(__float2half_rn(v0 * g_cs[col0]),
                                       __float2half_rn(v1 * g_cs[col0 + 1]));
                } else {
                    float2 y;
                    y.x = v0 * us + bias[col0];
                    y.y = v1 * us + bias[col0 + 1];
                    *(float2*)(out + (size_t)row * OUT_F + col0) = y;
                }
            }
        }
    }
}

// ---------------- persistent fused kernel ----------------
__global__ void __launch_bounds__(256, 1)
gemm_persistent(const float* __restrict__ Us, const float* __restrict__ bias,
                float* __restrict__ out) {
    extern __shared__ char smem[];
    __shared__ unsigned s_task;
    const uint32_t sb = smem_u32(smem);
    const int tid = threadIdx.x;

    for (;;) {
        if (tid == 0) s_task = atomicAdd(&g_ticket, 1u);
        __syncthreads();
        const unsigned task = s_task;
        if (task >= NTASKS) break;

        if (task < G1_TASKS) {
            const int m = task >> 2, n = task & 3;
            run_tile<0>(sb, m * BM, n * BN, 0.f, bias, out);
            __syncthreads();                       // all h stores done
            if (tid == 0) {
                __threadfence();                   // publish h before flagging
                atomicAdd(&g_flag[m], 1u);
            }
        } else {
            const unsigned u = task - G1_TASKS;
            const int m = u >> 4, n = u & 15;
            if (tid == 0) {                        // wait for all 4 G1 tiles of this m-block
                unsigned v;
                do {
                    asm volatile("ld.acquire.gpu.global.u32 %0, [%1];"
                                 : "=r"(v) : "l"(&g_flag[m]) : "memory");
                    if (v >= 4) break;
                    __nanosleep(128);
                } while (true);
            }
            __syncthreads();
            run_tile<1>(sb, m * BM, n * BN, Us[0], bias, out);
        }
        __syncthreads();                           // protect smem + s_task across tasks
    }
}

// ---------------- launch ----------------
extern "C" void kernel_launch(void* const* d_in, const int* in_sizes, int n_in,
                              void* d_out, int out_size) {
    const float* x    = (const float*)d_in[0];
    const int*   Ud   = (const int*)  d_in[1];
    const float* Us   = (const float*)d_in[2];
    const int*   Sd   = (const int*)  d_in[4];
    const float* Ss   = (const float*)d_in[5];
    const float* Szp  = (const float*)d_in[6];
    const int*   Vhd  = (const int*)  d_in[7];
    const float* Vhs  = (const float*)d_in[8];
    const float* bias = (const float*)d_in[10];
    float* out = (float*)d_out;
    (void)in_sizes; (void)n_in; (void)out_size;

    cudaFuncSetAttribute(gemm_persistent, cudaFuncAttributeMaxDynamicSharedMemorySize, SMEM_TOTAL);

    k_init<<<1, 64>>>();
    const int nx4 = NROWS * IN_F / 4;
    k_convert_x<<<(nx4 + 255) / 256, 256>>>(x, nx4);
    const int nw = RANK * IN_F / 4 + OUT_F * RANK / 4;
    k_convert_w2<<<(nw + 255) / 256, 256>>>(Vhd, Ud);
    k_colscale<<<(RANK + 255) / 256, 256>>>(Sd, Vhs, Ss, Szp);

    gemm_persistent<<<PERSIST, 256, SMEM_TOTAL>>>(Us, bias, out);
}

// round 11
// speedup vs baseline: 4.2232x; 1.0908x over previous
#include <cuda_runtime.h>
#include <cuda_fp16.h>
#include <cstdint>

#define NROWS 8192
#define IN_F  4096
#define OUT_F 4096
#define RANK  1024

#define BM 128
#define BN 256
#define BK 32
#define STRB 80
#define A_TILE (128 * STRB)
#define B_TILE (256 * STRB)
#define STG_B  (A_TILE + B_TILE)
#define STAGES 3
#define SMEM_TOTAL (STAGES * STG_B)   // 92160

#define G1_TASKS 256                  // 64 m x 4 n
#define G2_TASKS 1024                 // 64 m x 16 n
#define NTASKS   (G1_TASKS + G2_TASKS)
#define PERSIST  152

// ---------------- scratch ----------------
__device__ __half g_h [(size_t)NROWS * RANK];
__device__ __half g_vh[(size_t)RANK  * IN_F];
__device__ __half g_u [(size_t)OUT_F * RANK];
__device__ float  g_cs[RANK];
__device__ unsigned g_ticket;
__device__ unsigned g_flag[64];

// ---------------- prep ----------------
__global__ void k_colscale_init(const int* __restrict__ Sd, const float* __restrict__ vhs,
                                const float* __restrict__ ss, const float* __restrict__ szp) {
    int r = threadIdx.x;
    if (r < RANK) g_cs[r] = vhs[0] * ss[0] * ((float)Sd[r] - szp[0]);
    if (r < 64) g_flag[r] = 0;
    if (r == 0) g_ticket = 0;
}
__global__ void k_convert_w2(const int* __restrict__ Vhd, const int* __restrict__ Ud) {
    const int nv = RANK * IN_F / 4;
    const int nu = OUT_F * RANK / 4;
    int i = blockIdx.x * blockDim.x + threadIdx.x;
    const int* src; __half* dst; int j;
    if (i < nv)           { src = Vhd; dst = g_vh; j = i; }
    else if (i < nv + nu) { src = Ud;  dst = g_u;  j = i - nv; }
    else return;
    int4 v = ((const int4*)src)[j];
    *(__half2*)(dst + (size_t)j * 4)     = __halves2half2(__int2half_rn(v.x - 128), __int2half_rn(v.y - 128));
    *(__half2*)(dst + (size_t)j * 4 + 2) = __halves2half2(__int2half_rn(v.z - 128), __int2half_rn(v.w - 128));
}

// ---------------- PTX helpers ----------------
__device__ __forceinline__ void cp16(uint32_t dst, const void* src) {
    asm volatile("cp.async.cg.shared.global [%0], [%1], 16;" :: "r"(dst), "l"(src) : "memory");
}
#define CP_COMMIT() asm volatile("cp.async.commit_group;" ::: "memory")
#define CP_WAIT1()  asm volatile("cp.async.wait_group 1;" ::: "memory")
#define CP_WAIT0()  asm volatile("cp.async.wait_group 0;" ::: "memory")
__device__ __forceinline__ uint32_t smem_u32(const void* p) {
    uint32_t a;
    asm("{ .reg .u64 t; cvta.to.shared.u64 t, %1; cvt.u32.u64 %0, t; }" : "=r"(a) : "l"(p));
    return a;
}
__device__ __forceinline__ void hmma(float* d, uint32_t a0, uint32_t a1, uint32_t a2, uint32_t a3,
                                     uint32_t b0, uint32_t b1) {
    asm volatile(
        "mma.sync.aligned.m16n8k16.row.col.f32.f16.f16.f32 "
        "{%0,%1,%2,%3}, {%4,%5,%6,%7}, {%8,%9}, {%0,%1,%2,%3};\n"
        : "+f"(d[0]), "+f"(d[1]), "+f"(d[2]), "+f"(d[3])
        : "r"(a0), "r"(a1), "r"(a2), "r"(a3), "r"(b0), "r"(b1));
}
__device__ __forceinline__ void ldsm4(uint32_t& r0, uint32_t& r1, uint32_t& r2, uint32_t& r3,
                                      uint32_t addr) {
    asm volatile("ldmatrix.sync.aligned.m8n8.x4.shared.b16 {%0,%1,%2,%3}, [%4];"
                 : "=r"(r0), "=r"(r1), "=r"(r2), "=r"(r3) : "r"(addr));
}
__device__ __forceinline__ void sts16(uint32_t addr, uint32_t x, uint32_t y, uint32_t z, uint32_t w) {
    asm volatile("st.shared.v4.b32 [%0], {%1,%2,%3,%4};" :: "r"(addr), "r"(x), "r"(y), "r"(z), "r"(w));
}
__device__ __forceinline__ uint32_t h2u(__half2 h) {
    union { __half2 h; uint32_t u; } c; c.h = h; return c.u;
}

// ---------------- one GEMM tile task ----------------
// MODE 0: h = (fp16(x) @ Vh^T) * cs -> g_h ; A loaded fp32 + converted inline (K=4096)
// MODE 1: y = (h @ U^T) * Us + bias -> out f32                               (K=1024)
template<int MODE>
__device__ __forceinline__ void run_tile(uint32_t sb, int bm, int bn,
                                         const float* __restrict__ xf,
                                         float us, const float* __restrict__ bias,
                                         float* __restrict__ out) {
    constexpr int K = (MODE == 0) ? IN_F : RANK;
    constexpr int T = K / BK;

    const int tid  = threadIdx.x;
    const int lane = tid & 31;
    const int wid  = tid >> 5;
    const int wm   = wid & 1;
    const int wn   = wid >> 1;

    const __half* Bw = (MODE == 0) ? g_vh : g_u;

    float acc[4][8][4];
#pragma unroll
    for (int a = 0; a < 4; ++a)
#pragma unroll
        for (int b = 0; b < 8; ++b)
#pragma unroll
            for (int c = 0; c < 4; ++c) acc[a][b][c] = 0.f;

    const int r0 = tid >> 2;
    const int c0 = tid & 3;

    // B producer (cp.async, both modes)
    auto issueB = [&](int t) {
        const uint32_t stg = sb + (t % STAGES) * STG_B;
        const int k0 = t * BK;
        const size_t bo = (size_t)(bn + r0) * K + k0 + c0 * 8;
        const uint32_t db = stg + A_TILE + r0 * STRB + c0 * 16;
#pragma unroll
        for (int q = 0; q < 4; ++q)
            cp16(db + q * 64 * STRB, Bw + bo + (size_t)q * 64 * K);
    };

    // A producer MODE 0: fp32 x -> regs -> fp16 smem
    float4 ar[4];
    auto ldA = [&](int t) {
        const int k0 = t * BK;
        const float* p = xf + (size_t)(bm + r0) * IN_F + k0 + c0 * 8;
        ar[0] = *(const float4*)p;
        ar[1] = *(const float4*)(p + 4);
        p += (size_t)64 * IN_F;
        ar[2] = *(const float4*)p;
        ar[3] = *(const float4*)(p + 4);
    };
    auto stA = [&](int t) {
        const uint32_t da = sb + (t % STAGES) * STG_B + r0 * STRB + c0 * 16;
#pragma unroll
        for (int q = 0; q < 2; ++q) {
            const uint32_t u0 = h2u(__floats2half2_rn(ar[2*q].x,   ar[2*q].y));
            const uint32_t u1 = h2u(__floats2half2_rn(ar[2*q].z,   ar[2*q].w));
            const uint32_t u2 = h2u(__floats2half2_rn(ar[2*q+1].x, ar[2*q+1].y));
            const uint32_t u3 = h2u(__floats2half2_rn(ar[2*q+1].z, ar[2*q+1].w));
            sts16(da + q * 64 * STRB, u0, u1, u2, u3);
        }
    };

    // A producer MODE 1 (h is fp16 already)
    auto issueA1 = [&](int t) {
        const uint32_t stg = sb + (t % STAGES) * STG_B;
        const int k0 = t * BK;
        const size_t ao = (size_t)(bm + r0) * K + k0 + c0 * 8;
        const uint32_t da = stg + r0 * STRB + c0 * 16;
        cp16(da,             g_h + ao);
        cp16(da + 64 * STRB, g_h + ao + (size_t)64 * K);
    };

    // ---- prologue: stages 0,1 ----
    if (MODE == 0) { ldA(0); stA(0); ldA(1); stA(1); }
    else           { issueA1(0); }
    issueB(0); CP_COMMIT();
    if (MODE == 1) issueA1(1);
    issueB(1); CP_COMMIT();

    const int grp = lane >> 3, win = lane & 7;
    const uint32_t aoff = (wm * 64 + ((grp & 1) << 3) + win) * STRB + ((grp >> 1) << 4);
    const uint32_t boff = A_TILE + (wn * 64 + ((grp >> 1) << 3) + win) * STRB + ((grp & 1) << 4);

    for (int t = 0; t < T; ++t) {
        CP_WAIT1();
        __syncthreads();
        if (t + 2 < T) {
            if (MODE == 0) ldA(t + 2); else issueA1(t + 2);
            issueB(t + 2);
        }
        CP_COMMIT();

        const uint32_t stg = sb + (t % STAGES) * STG_B;
#pragma unroll
        for (int ks = 0; ks < 2; ++ks) {
            const uint32_t co = ks * 32;
            uint32_t bf[8][2];
#pragma unroll
            for (int ntp = 0; ntp < 4; ++ntp)
                ldsm4(bf[2*ntp][0], bf[2*ntp][1], bf[2*ntp+1][0], bf[2*ntp+1][1],
                      stg + boff + ntp * 16 * STRB + co);
#pragma unroll
            for (int mt = 0; mt < 4; ++mt) {
                uint32_t a0, a1, a2, a3;
                ldsm4(a0, a1, a2, a3, stg + aoff + mt * 16 * STRB + co);
#pragma unroll
                for (int nt = 0; nt < 8; ++nt)
                    hmma(acc[mt][nt], a0, a1, a2, a3, bf[nt][0], bf[nt][1]);
            }
        }
        if (MODE == 0 && t + 2 < T) stA(t + 2);   // buffer (t+2)%3 free: last consumer was iter t-1
    }
    CP_WAIT0();

    const int fr = lane >> 2;
    const int fq = (lane & 3) * 2;
#pragma unroll
    for (int mt = 0; mt < 4; ++mt) {
#pragma unroll
        for (int nt = 0; nt < 8; ++nt) {
            const int row0 = bm + wm * 64 + mt * 16 + fr;
            const int col0 = bn + wn * 64 + nt * 8 + fq;
#pragma unroll
            for (int h = 0; h < 2; ++h) {
                const int row = row0 + h * 8;
                const float v0 = acc[mt][nt][2 * h + 0];
                const float v1 = acc[mt][nt][2 * h + 1];
                if (MODE == 0) {
                    *(__half2*)(g_h + (size_t)row * RANK + col0) =
                        __halves2half2(__float2half_rn(v0 * g_cs[col0]),
                                       __float2half_rn(v1 * g_cs[col0 + 1]));
                } else {
                    float2 y;
                    y.x = v0 * us + bias[col0];
                    y.y = v1 * us + bias[col0 + 1];
                    *(float2*)(out + (size_t)row * OUT_F + col0) = y;
                }
            }
        }
    }
}

// ---------------- persistent fused kernel ----------------
__global__ void __launch_bounds__(256, 1)
gemm_persistent(const float* __restrict__ xf, const float* __restrict__ Us,
                const float* __restrict__ bias, float* __restrict__ out) {
    extern __shared__ char smem[];
    __shared__ unsigned s_task;
    const uint32_t sb = smem_u32(smem);
    const int tid = threadIdx.x;

    for (;;) {
        if (tid == 0) s_task = atomicAdd(&g_ticket, 1u);
        __syncthreads();
        const unsigned task = s_task;
        if (task >= NTASKS) break;

        if (task < G1_TASKS) {
            const int m = task >> 2, n = task & 3;
            run_tile<0>(sb, m * BM, n * BN, xf, 0.f, bias, out);
            __syncthreads();
            if (tid == 0) {
                __threadfence();
                atomicAdd(&g_flag[m], 1u);
            }
        } else {
            const unsigned u = task - G1_TASKS;
            const int m = u >> 4, n = u & 15;
            if (tid == 0) {
                unsigned v;
                do {
                    asm volatile("ld.acquire.gpu.global.u32 %0, [%1];"
                                 : "=r"(v) : "l"(&g_flag[m]) : "memory");
                    if (v >= 4) break;
                    __nanosleep(128);
                } while (true);
            }
            __syncthreads();
            run_tile<1>(sb, m * BM, n * BN, xf, Us[0], bias, out);
        }
        __syncthreads();
    }
}

// ---------------- launch ----------------
extern "C" void kernel_launch(void* const* d_in, const int* in_sizes, int n_in,
                              void* d_out, int out_size) {
    const float* x    = (const float*)d_in[0];
    const int*   Ud   = (const int*)  d_in[1];
    const float* Us   = (const float*)d_in[2];
    const int*   Sd   = (const int*)  d_in[4];
    const float* Ss   = (const float*)d_in[5];
    const float* Szp  = (const float*)d_in[6];
    const int*   Vhd  = (const int*)  d_in[7];
    const float* Vhs  = (const float*)d_in[8];
    const float* bias = (const float*)d_in[10];
    float* out = (float*)d_out;
    (void)in_sizes; (void)n_in; (void)out_size;

    cudaFuncSetAttribute(gemm_persistent, cudaFuncAttributeMaxDynamicSharedMemorySize, SMEM_TOTAL);

    k_colscale_init<<<1, 1024>>>(Sd, Vhs, Ss, Szp);
    const int nw = RANK * IN_F / 4 + OUT_F * RANK / 4;
    k_convert_w2<<<(nw + 255) / 256, 256>>>(Vhd, Ud);

    gemm_persistent<<<PERSIST, 256, SMEM_TOTAL>>>(x, Us, bias, out);
}